// round 15
// baseline (speedup 1.0000x reference)
#include <cuda_runtime.h>
#include <cuda_fp16.h>
#include <math.h>
#include <stdint.h>

#define NN   30000
#define EE   480000
#define EP   (EE + NN)      // 510000 (edges + self loops)
#define INC  128
#define H1   5
#define C1   64
#define F1   (H1 * C1)      // 320
#define OUTC 64
#define PEC  100000
#define NPAIR (2 * PEC)
#define NEG_SLOPE 0.2f

// ---------------- scratch ----------------
__device__ __half g_h1[NN * F1];
__device__ __half g_h2[NN * OUTC];
__device__ __half g_z2[NN * OUTC];
__device__ float  g_as1[NN * H1];
__device__ float  g_ad1[NN * H1];
__device__ float  g_as2[NN];
__device__ float  g_ad2[NN];
__device__ int    g_cnt[NN];
__device__ int    g_rowptr[NN + 1];
__device__ int    g_cursor[NN];
__device__ int    g_csr_src[EP];
__device__ __half g_xh[NN * INC];
__device__ __half g_z1h[NN * F1];
__device__ __half g_w1h[F1 * INC];   // W1^T [320,128]
__device__ __half g_w2h[OUTC * F1];  // W2^T [64,320]

// ---------------- mma / async helpers (base PTX, sm_80+) ----------------
__device__ __forceinline__ uint32_t smem_u32(const void* p) {
    uint32_t a;
    asm("{ .reg .u64 t; cvta.to.shared.u64 t, %1; cvt.u32.u64 %0, t; }" : "=r"(a) : "l"(p));
    return a;
}
__device__ __forceinline__ void ldsm_x4(uint32_t& r0, uint32_t& r1, uint32_t& r2,
                                        uint32_t& r3, uint32_t addr) {
    asm volatile("ldmatrix.sync.aligned.m8n8.x4.shared.b16 {%0,%1,%2,%3}, [%4];"
                 : "=r"(r0), "=r"(r1), "=r"(r2), "=r"(r3) : "r"(addr));
}
__device__ __forceinline__ void mma_f16(float* c, const uint32_t* a, const uint32_t* b) {
    asm volatile(
        "mma.sync.aligned.m16n8k16.row.col.f32.f16.f16.f32 "
        "{%0,%1,%2,%3}, {%4,%5,%6,%7}, {%8,%9}, {%0,%1,%2,%3};"
        : "+f"(c[0]), "+f"(c[1]), "+f"(c[2]), "+f"(c[3])
        : "r"(a[0]), "r"(a[1]), "r"(a[2]), "r"(a[3]), "r"(b[0]), "r"(b[1]));
}
__device__ __forceinline__ void cp_async16(uint32_t s, const void* g) {
    asm volatile("cp.async.cg.shared.global [%0], [%1], 16;" :: "r"(s), "l"(g));
}
#define CP_COMMIT()  asm volatile("cp.async.commit_group;")
#define CP_WAIT(n)   asm volatile("cp.async.wait_group %0;" :: "n"(n))

// ---- prep_x: float4 x-convert + W1 transpose (everything gemm1 needs) -------
__global__ void prep_x(const float* __restrict__ x, const float* __restrict__ W1,
                       __half* __restrict__ xh, __half* __restrict__ w1h) {
    int i = blockIdx.x * blockDim.x + threadIdx.x;
    if (i < NN * INC / 4) {
        float4 v = ((const float4*)x)[i];
        ((__half2*)xh)[i * 2]     = __floats2half2_rn(v.x, v.y);
        ((__half2*)xh)[i * 2 + 1] = __floats2half2_rn(v.z, v.w);
    }
    if (i < INC * F1) {                       // out[n*INC + k] = W1[k*F1 + n]
        int n = i / INC, k = i % INC;
        w1h[i] = __float2half(W1[(size_t)k * F1 + n]);
    }
}

// ---- prep_rest: edge histogram (4-wide) + W2 transpose (overlaps gemm1) -----
__global__ void prep_rest(const float* __restrict__ W2, const int* __restrict__ dst,
                          __half* __restrict__ w2h, int* __restrict__ cnt) {
    int i = blockIdx.x * blockDim.x + threadIdx.x;
    {
        int e0 = i * 4;
        if (e0 < EP) {
            int d[4];
            #pragma unroll
            for (int q = 0; q < 4; q++) {
                int e = e0 + q;
                d[q] = (e < EP) ? ((e < EE) ? dst[e] : e - EE) : -1;
            }
            #pragma unroll
            for (int q = 0; q < 4; q++)
                if (d[q] >= 0) atomicAdd(&cnt[d[q]], 1);
        }
    }
    if (i < F1 * OUTC) {                      // out[n*F1 + k] = W2[k*OUTC + n]
        int n = i / F1, k = i % F1;
        w2h[i] = __float2half(W2[(size_t)k * OUTC + n]);
    }
}

// ---------------- CSR build ----------------
__global__ void scan_all(const int* __restrict__ cnt, int* __restrict__ rowptr,
                         int* __restrict__ cursor) {
    __shared__ int part[1024];
    const int t = threadIdx.x;
    const int PER = (NN + 1023) / 1024;   // 30
    int local[PER];
    int base = t * PER;
    int sum = 0;
    #pragma unroll
    for (int i = 0; i < PER; i++) {
        int idx = base + i;
        int v = (idx < NN) ? cnt[idx] : 0;
        local[i] = sum;
        sum += v;
    }
    part[t] = sum;
    __syncthreads();
    for (int o = 1; o < 1024; o <<= 1) {
        int u = (t >= o) ? part[t - o] : 0;
        __syncthreads();
        part[t] += u;
        __syncthreads();
    }
    int off = (t > 0) ? part[t - 1] : 0;
    #pragma unroll
    for (int i = 0; i < PER; i++) {
        int idx = base + i;
        if (idx < NN) {
            int v = off + local[i];
            rowptr[idx] = v;
            cursor[idx] = v;
        }
    }
    if (t == 0) rowptr[NN] = EP;
}

__global__ void fill_csr(const int* __restrict__ src, const int* __restrict__ dst,
                         int* __restrict__ cursor, int* __restrict__ csr_src) {
    int i = blockIdx.x * blockDim.x + threadIdx.x;
    int e0 = i * 4;
    if (e0 >= EP) return;
    int s[4], d[4];
    #pragma unroll
    for (int q = 0; q < 4; q++) {
        int e = e0 + q;
        if (e < EP) {
            s[q] = (e < EE) ? src[e] : e - EE;
            d[q] = (e < EE) ? dst[e] : e - EE;
        } else d[q] = -1;
    }
    #pragma unroll
    for (int q = 0; q < 4; q++) {
        if (d[q] >= 0) {
            int pos = atomicAdd(&cursor[d[q]], 1);
            csr_src[pos] = s[q];
        }
    }
}

// ======== gemm1: M-tile 64, A-resident, double-buffered B via cp.async ========
#define STRA 136
#define SMA_A  0
#define SMA_B0 (64 * STRA)
#define SMA_B1 (128 * STRA)
#define SMA_RED (192 * STRA)
#define SMA_ELEMS (192 * STRA + 1024)

__global__ void __launch_bounds__(256, 4) gemm1_fused(
    const __half* __restrict__ A, const __half* __restrict__ B,
    __half* __restrict__ Ch,
    float* __restrict__ as_, float* __restrict__ ad_,
    const float* __restrict__ att_s, const float* __restrict__ att_d, int M)
{
    extern __shared__ __align__(16) __half smem[];
    const int tid = threadIdx.x;
    const int wid = tid >> 5, lane = tid & 31;
    const int wm = wid >> 1;
    const int wn = wid & 1;
    const int row0 = blockIdx.x * 64;
    const uint32_t sb = smem_u32(smem);

    #pragma unroll
    for (int i = 0; i < 4; i++) {
        int u = tid + i * 256;
        int r = u >> 4, c8 = (u & 15) * 8;
        int gr = row0 + r;
        uint4 v = (gr < M) ? *(const uint4*)(A + (size_t)gr * INC + c8)
                           : make_uint4(0u, 0u, 0u, 0u);
        *(uint4*)(smem + SMA_A + r * STRA + c8) = v;
    }
    #pragma unroll
    for (int i = 0; i < 4; i++) {
        int u = tid + i * 256;
        int r = u >> 4, c8 = (u & 15) * 8;
        cp_async16(sb + (uint32_t)(SMA_B0 + r * STRA + c8) * 2,
                   B + (size_t)r * INC + c8);
    }
    CP_COMMIT();

    const int a_row = lane & 15;
    const int a_koff = (lane >> 4) * 8;
    const int b_row = (lane & 7) + ((lane >> 4) << 3);
    const int b_koff = ((lane >> 3) & 1) * 8;
    const int erow = lane >> 2;
    const int ecol = (lane & 3) * 2;
    float* red = (float*)(smem + SMA_RED);

    for (int nt = 0; nt < H1; nt++) {
        if (nt + 1 < H1) {
            int bofs_n = ((nt + 1) & 1) ? SMA_B1 : SMA_B0;
            #pragma unroll
            for (int i = 0; i < 4; i++) {
                int u = tid + i * 256;
                int r = u >> 4, c8 = (u & 15) * 8;
                cp_async16(sb + (uint32_t)(bofs_n + r * STRA + c8) * 2,
                           B + (size_t)((nt + 1) * 64 + r) * INC + c8);
            }
            CP_COMMIT();
            CP_WAIT(1);
        } else {
            CP_WAIT(0);
        }
        __syncthreads();

        const int bofs = (nt & 1) ? SMA_B1 : SMA_B0;

        float acc[4][4];
        #pragma unroll
        for (int j = 0; j < 4; j++)
            #pragma unroll
            for (int q = 0; q < 4; q++) acc[j][q] = 0.f;

        #pragma unroll
        for (int ks = 0; ks < 8; ks++) {
            uint32_t ar[4], br[4][2];
            {
                int off = (wm * 16 + a_row) * STRA + ks * 16 + a_koff;
                ldsm_x4(ar[0], ar[1], ar[2], ar[3], sb + (uint32_t)(SMA_A + off) * 2);
            }
            #pragma unroll
            for (int np = 0; np < 2; np++) {
                int off = (wn * 32 + np * 16 + b_row) * STRA + ks * 16 + b_koff;
                ldsm_x4(br[np * 2][0], br[np * 2][1], br[np * 2 + 1][0], br[np * 2 + 1][1],
                        sb + (uint32_t)(bofs + off) * 2);
            }
            #pragma unroll
            for (int ni = 0; ni < 4; ni++)
                mma_f16(acc[ni], ar, br[ni]);
        }

        const int col0 = nt * 64;
        {
            int r0 = row0 + wm * 16 + erow;
            #pragma unroll
            for (int ni = 0; ni < 4; ni++) {
                int cc = col0 + wn * 32 + ni * 8 + ecol;
                if (r0 < M)
                    *(__half2*)&Ch[(size_t)r0 * F1 + cc] =
                        __floats2half2_rn(acc[ni][0], acc[ni][1]);
                if (r0 + 8 < M)
                    *(__half2*)&Ch[(size_t)(r0 + 8) * F1 + cc] =
                        __floats2half2_rn(acc[ni][2], acc[ni][3]);
            }
        }

        const float* att_sg = att_s + nt * 64;
        const float* att_dg = att_d + nt * 64;
        float asp[2] = {}, adp[2] = {};
        #pragma unroll
        for (int ni = 0; ni < 4; ni++) {
            int cb = wn * 32 + ni * 8 + ecol;
            float s0 = att_sg[cb], s1 = att_sg[cb + 1];
            float d0 = att_dg[cb], d1 = att_dg[cb + 1];
            asp[0] += acc[ni][0] * s0 + acc[ni][1] * s1;
            asp[1] += acc[ni][2] * s0 + acc[ni][3] * s1;
            adp[0] += acc[ni][0] * d0 + acc[ni][1] * d1;
            adp[1] += acc[ni][2] * d0 + acc[ni][3] * d1;
        }
        #pragma unroll
        for (int o = 1; o < 4; o <<= 1) {
            #pragma unroll
            for (int mr = 0; mr < 2; mr++) {
                asp[mr] += __shfl_xor_sync(0xFFFFFFFFu, asp[mr], o);
                adp[mr] += __shfl_xor_sync(0xFFFFFFFFu, adp[mr], o);
            }
        }
        if ((lane & 3) == 0) {
            #pragma unroll
            for (int mr = 0; mr < 2; mr++) {
                int rl = wm * 16 + erow + mr * 8;
                red[rl * 4 + wn]     = asp[mr];
                red[rl * 4 + 2 + wn] = adp[mr];
            }
        }
        __syncthreads();
        if (tid < 64) {
            int r = row0 + tid;
            if (r < M) {
                as_[(size_t)r * H1 + nt] = red[tid * 4 + 0] + red[tid * 4 + 1];
                ad_[(size_t)r * H1 + nt] = red[tid * 4 + 2] + red[tid * 4 + 3];
            }
        }
    }
}

// ======== gemm2: chunked-K fp16 HMMA (K=320), N tile 64, logits fused ========
#define STR 72
#define SM_A 0
#define SM_B (128 * STR)
#define SM_ELEMS (128 * STR + 64 * STR)

__global__ void __launch_bounds__(256, 4) mma_gemm(
    const __half* __restrict__ A, const __half* __restrict__ B,
    __half* __restrict__ Ch,
    float* __restrict__ as_, float* __restrict__ ad_,
    const float* __restrict__ att_s, const float* __restrict__ att_d,
    int M, int Ncol, int K, int H)
{
    extern __shared__ __align__(16) __half smem[];
    const int tid = threadIdx.x;
    const int wid = tid >> 5, lane = tid & 31;
    const int wm = wid >> 1;
    const int wn = wid & 1;
    const int row0 = blockIdx.y * 128;
    const int col0 = blockIdx.x * 64;
    const int hx = blockIdx.x;
    const uint32_t sb = smem_u32(smem);

    float acc[2][4][4];
    #pragma unroll
    for (int i = 0; i < 2; i++)
        #pragma unroll
        for (int j = 0; j < 4; j++)
            #pragma unroll
            for (int q = 0; q < 4; q++) acc[i][j][q] = 0.f;

    const int a_row = lane & 15;
    const int a_koff = (lane >> 4) * 8;
    const int b_row = (lane & 7) + ((lane >> 4) << 3);
    const int b_koff = ((lane >> 3) & 1) * 8;

    for (int K0 = 0; K0 < K; K0 += 64) {
        #pragma unroll
        for (int i = 0; i < 4; i++) {
            int u = tid + i * 256;
            int r = u >> 3, c8 = (u & 7) * 8;
            int dstoff = r * STR + c8;
            int gr = row0 + r;
            uint4 v = (gr < M) ? *(const uint4*)(A + (size_t)gr * K + K0 + c8)
                               : make_uint4(0u, 0u, 0u, 0u);
            *(uint4*)(smem + SM_A + dstoff) = v;
        }
        #pragma unroll
        for (int i = 0; i < 2; i++) {
            int u = tid + i * 256;
            int r = u >> 3, c8 = (u & 7) * 8;
            int dstoff = r * STR + c8;
            *(uint4*)(smem + SM_B + dstoff) = *(const uint4*)(B + (size_t)(col0 + r) * K + K0 + c8);
        }
        __syncthreads();

        #pragma unroll
        for (int ks = 0; ks < 4; ks++) {
            uint32_t ar[2][4], br[4][2];
            #pragma unroll
            for (int mi = 0; mi < 2; mi++) {
                int off = (wm * 32 + mi * 16 + a_row) * STR + ks * 16 + a_koff;
                ldsm_x4(ar[mi][0], ar[mi][1], ar[mi][2], ar[mi][3],
                        sb + (uint32_t)(SM_A + off) * 2);
            }
            #pragma unroll
            for (int np = 0; np < 2; np++) {
                int off = (wn * 32 + np * 16 + b_row) * STR + ks * 16 + b_koff;
                ldsm_x4(br[np * 2][0], br[np * 2][1], br[np * 2 + 1][0], br[np * 2 + 1][1],
                        sb + (uint32_t)(SM_B + off) * 2);
            }
            #pragma unroll
            for (int mi = 0; mi < 2; mi++)
                #pragma unroll
                for (int ni = 0; ni < 4; ni++)
                    mma_f16(acc[mi][ni], ar[mi], br[ni]);
        }
        __syncthreads();
    }

    const int erow = lane >> 2;
    const int ecol = (lane & 3) * 2;

    #pragma unroll
    for (int mi = 0; mi < 2; mi++) {
        int r0 = row0 + wm * 32 + mi * 16 + erow;
        #pragma unroll
        for (int ni = 0; ni < 4; ni++) {
            int cc = col0 + wn * 32 + ni * 8 + ecol;
            if (r0 < M)
                *(__half2*)&Ch[(size_t)r0 * Ncol + cc] =
                    __floats2half2_rn(acc[mi][ni][0], acc[mi][ni][1]);
            if (r0 + 8 < M)
                *(__half2*)&Ch[(size_t)(r0 + 8) * Ncol + cc] =
                    __floats2half2_rn(acc[mi][ni][2], acc[mi][ni][3]);
        }
    }

    const float* att_sg = att_s + hx * 64;
    const float* att_dg = att_d + hx * 64;
    float asp[2][2] = {}, adp[2][2] = {};
    #pragma unroll
    for (int mi = 0; mi < 2; mi++)
        #pragma unroll
        for (int ni = 0; ni < 4; ni++) {
            int cb = wn * 32 + ni * 8 + ecol;
            float s0 = att_sg[cb], s1 = att_sg[cb + 1];
            float d0 = att_dg[cb], d1 = att_dg[cb + 1];
            asp[mi][0] += acc[mi][ni][0] * s0 + acc[mi][ni][1] * s1;
            asp[mi][1] += acc[mi][ni][2] * s0 + acc[mi][ni][3] * s1;
            adp[mi][0] += acc[mi][ni][0] * d0 + acc[mi][ni][1] * d1;
            adp[mi][1] += acc[mi][ni][2] * d0 + acc[mi][ni][3] * d1;
        }
    #pragma unroll
    for (int o = 1; o < 4; o <<= 1) {
        #pragma unroll
        for (int mi = 0; mi < 2; mi++)
            #pragma unroll
            for (int mr = 0; mr < 2; mr++) {
                asp[mi][mr] += __shfl_xor_sync(0xFFFFFFFFu, asp[mi][mr], o);
                adp[mi][mr] += __shfl_xor_sync(0xFFFFFFFFu, adp[mi][mr], o);
            }
    }
    float* red = (float*)smem;
    if ((lane & 3) == 0) {
        #pragma unroll
        for (int mi = 0; mi < 2; mi++)
            #pragma unroll
            for (int mr = 0; mr < 2; mr++) {
                int rl = wm * 32 + mi * 16 + erow + mr * 8;
                red[rl * 4 + wn]     = asp[mi][mr];
                red[rl * 4 + 2 + wn] = adp[mi][mr];
            }
    }
    __syncthreads();
    if (tid < 128) {
        int r = row0 + tid;
        if (r < M) {
            as_[(size_t)r * H + hx] = red[tid * 4 + 0] + red[tid * 4 + 1];
            ad_[(size_t)r * H + hx] = red[tid * 4 + 2] + red[tid * 4 + 3];
        }
    }
}

// ---------------- fused softmax + aggregate + relu, layer 1 ----------------
__global__ void agg1(const int* __restrict__ rowptr, const int* __restrict__ csr_src,
                     const float* __restrict__ as_, const float* __restrict__ ad_,
                     const __half* __restrict__ h, const float* __restrict__ bias,
                     __half* __restrict__ zh) {
    __shared__ int   sh_src[32];
    __shared__ float sh_ex[160];
    const int d = blockIdx.x;
    const int c = threadIdx.x;
    const int hh = c >> 5;
    const int start = rowptr[d], end = rowptr[d + 1];
    const __half2* hp = (const __half2*)h;

    float ax = 0.f, ay = 0.f, sumex = 0.f;
    for (int j0 = start; j0 < end; j0 += 32) {
        int m = min(32, end - j0);
        {
            int j = c & 31, hq = c >> 5;
            if (j < m) {
                int s = csr_src[j0 + j];
                if (hq == 0) sh_src[j] = s;
                float e = as_[s * H1 + hq] + ad_[d * H1 + hq];
                e = (e > 0.f) ? e : NEG_SLOPE * e;
                sh_ex[hq * 32 + j] = __expf(e);
            }
        }
        __syncthreads();
        #pragma unroll 4
        for (int j = 0; j < m; j++) {
            float ex = sh_ex[hh * 32 + j];
            sumex += ex;
            float2 f = __half22float2(hp[(size_t)sh_src[j] * (F1 / 2) + c]);
            ax += ex * f.x;
            ay += ex * f.y;
        }
        __syncthreads();
    }
    float inv = 1.f / (sumex + 1e-16f);
    float v0 = ax * inv + bias[2 * c];
    float v1 = ay * inv + bias[2 * c + 1];
    v0 = (v0 > 0.f) ? v0 : 0.f;
    v1 = (v1 > 0.f) ? v1 : 0.f;
    ((__half2*)zh)[(size_t)d * (F1 / 2) + c] = __floats2half2_rn(v0, v1);
}

// ------- fused softmax + aggregate, layer 2: 4 nodes per 128-thr block -------
__global__ void agg2(const int* __restrict__ rowptr, const int* __restrict__ csr_src,
                     const float* __restrict__ as_, const float* __restrict__ ad_,
                     const __half* __restrict__ h, const float* __restrict__ bias,
                     __half* __restrict__ z) {
    const int d = blockIdx.x * 4 + (threadIdx.x >> 5);
    const int c = threadIdx.x & 31;
    if (d >= NN) return;
    const int start = rowptr[d], end = rowptr[d + 1];
    const __half2* hp = (const __half2*)h;

    float ax = 0.f, ay = 0.f, sumex = 0.f;
    for (int j0 = start; j0 < end; j0 += 32) {
        int m = min(32, end - j0);
        int s_c = 0; float ex_c = 0.f;
        if (c < m) {
            s_c = csr_src[j0 + c];
            float e = as_[s_c] + ad_[d];
            e = (e > 0.f) ? e : NEG_SLOPE * e;
            ex_c = __expf(e);
        }
        #pragma unroll 4
        for (int j = 0; j < m; j++) {
            float ex = __shfl_sync(0xFFFFFFFFu, ex_c, j);
            int   s  = __shfl_sync(0xFFFFFFFFu, s_c, j);
            sumex += ex;
            float2 f = __half22float2(hp[(size_t)s * (OUTC / 2) + c]);
            ax += ex * f.x;
            ay += ex * f.y;
        }
    }
    float inv = 1.f / (sumex + 1e-16f);
    ((__half2*)z)[(size_t)d * (OUTC / 2) + c] =
        __floats2half2_rn(ax * inv + bias[2 * c], ay * inv + bias[2 * c + 1]);
}

// ---- decode: 8 pairs per warp (2 per 8-lane subgroup), uint4 loads, MLP=4 ----
__global__ void decode(const int* __restrict__ pos, const int* __restrict__ neg,
                       const __half* __restrict__ z, float* __restrict__ out) {
    int g = blockIdx.x * blockDim.x + threadIdx.x;
    int w = g >> 5, lane = g & 31;
    int sub = lane >> 3;
    int l = lane & 7;
    int p0 = w * 8 + sub * 2;        // this subgroup handles pairs p0, p0+1
    if (p0 >= NPAIR) return;
    float v[2] = {0.f, 0.f};
    #pragma unroll
    for (int t = 0; t < 2; t++) {
        int p = p0 + t;
        if (p >= NPAIR) break;
        int i, j;
        if (p < PEC) { i = pos[p];       j = pos[PEC + p]; }
        else         { i = neg[p - PEC]; j = neg[PEC + p - PEC]; }
        uint4 a = ((const uint4*)(z + (size_t)i * OUTC))[l];
        uint4 b = ((const uint4*)(z + (size_t)j * OUTC))[l];
        const __half2* ah = (const __half2*)&a;
        const __half2* bh = (const __half2*)&b;
        #pragma unroll
        for (int q = 0; q < 4; q++) {
            float2 fa = __half22float2(ah[q]);
            float2 fb = __half22float2(bh[q]);
            v[t] += fa.x * fb.x + fa.y * fb.y;
        }
    }
    #pragma unroll
    for (int o = 4; o > 0; o >>= 1) {
        v[0] += __shfl_down_sync(0xFFFFFFFFu, v[0], o, 8);
        v[1] += __shfl_down_sync(0xFFFFFFFFu, v[1], o, 8);
    }
    if (l == 0) {
        out[p0] = v[0];
        if (p0 + 1 < NPAIR) out[p0 + 1] = v[1];
    }
}

// ---------------- launch ----------------
extern "C" void kernel_launch(void* const* d_in, const int* in_sizes, int n_in,
                              void* d_out, int out_size) {
    const float* x      = (const float*)d_in[0];
    const int*   ei     = (const int*)  d_in[1];
    const int*   pos    = (const int*)  d_in[2];
    const int*   neg    = (const int*)  d_in[3];
    const float* W1     = (const float*)d_in[4];
    const float* att_s1 = (const float*)d_in[5];
    const float* att_d1 = (const float*)d_in[6];
    const float* b1     = (const float*)d_in[7];
    const float* W2     = (const float*)d_in[8];
    const float* att_s2 = (const float*)d_in[9];
    const float* att_d2 = (const float*)d_in[10];
    const float* b2     = (const float*)d_in[11];
    float* out = (float*)d_out;

    const int* src = ei;
    const int* dst = ei + EE;

    __half *h1, *h2, *z2, *xh, *z1h, *w1h, *w2h;
    float *as1, *ad1, *as2, *ad2;
    int *cnt, *rowptr, *cursor, *csr_src;
    cudaGetSymbolAddress((void**)&h1, g_h1);
    cudaGetSymbolAddress((void**)&h2, g_h2);
    cudaGetSymbolAddress((void**)&z2, g_z2);
    cudaGetSymbolAddress((void**)&as1, g_as1);
    cudaGetSymbolAddress((void**)&ad1, g_ad1);
    cudaGetSymbolAddress((void**)&as2, g_as2);
    cudaGetSymbolAddress((void**)&ad2, g_ad2);
    cudaGetSymbolAddress((void**)&cnt, g_cnt);
    cudaGetSymbolAddress((void**)&rowptr, g_rowptr);
    cudaGetSymbolAddress((void**)&cursor, g_cursor);
    cudaGetSymbolAddress((void**)&csr_src, g_csr_src);
    cudaGetSymbolAddress((void**)&xh, g_xh);
    cudaGetSymbolAddress((void**)&z1h, g_z1h);
    cudaGetSymbolAddress((void**)&w1h, g_w1h);
    cudaGetSymbolAddress((void**)&w2h, g_w2h);

    const int TPB = 256;
    constexpr int SMEM_G1 = SMA_ELEMS * 2;
    constexpr int SMEM_G2 = SM_ELEMS * 2;
    cudaFuncSetAttribute(gemm1_fused, cudaFuncAttributeMaxDynamicSharedMemorySize, SMEM_G1);
    cudaFuncSetAttribute(mma_gemm, cudaFuncAttributeMaxDynamicSharedMemorySize, SMEM_G2);

    cudaStream_t s2;
    cudaStreamCreate(&s2);
    cudaEvent_t evX, evG1;
    cudaEventCreateWithFlags(&evX, cudaEventDisableTiming);
    cudaEventCreateWithFlags(&evG1, cudaEventDisableTiming);

    // ---- minimal prefix: zero cnt + x/W1 prep, then fork gemm1 ----
    cudaMemsetAsync(cnt, 0, NN * sizeof(int));
    prep_x<<<(NN * INC / 4 + TPB - 1) / TPB, TPB>>>(x, W1, xh, w1h);
    cudaEventRecord(evX, 0);

    cudaStreamWaitEvent(s2, evX, 0);
    gemm1_fused<<<(NN + 63) / 64, 256, SMEM_G1, s2>>>(
        xh, w1h, h1, as1, ad1, att_s1, att_d1, NN);
    cudaEventRecord(evG1, s2);

    // ---- stream0: histogram + W2 + CSR build (overlaps gemm1) ----
    prep_rest<<<(EP / 4 + TPB - 1) / TPB, TPB>>>(W2, dst, w2h, cnt);
    scan_all<<<1, 1024>>>(cnt, rowptr, cursor);
    fill_csr<<<(EP / 4 + TPB) / TPB, TPB>>>(src, dst, cursor, csr_src);

    cudaStreamWaitEvent(0, evG1, 0);

    // ---- layer 1 aggregate -> layer 2 GEMM -> aggregate -> decode ----
    agg1<<<NN, 160>>>(rowptr, csr_src, as1, ad1, h1, b1, z1h);
    {
        dim3 grid(1, (NN + 127) / 128);
        mma_gemm<<<grid, 256, SMEM_G2>>>(z1h, w2h, h2,
                                         as2, ad2, att_s2, att_d2, NN, OUTC, F1, 1);
    }
    agg2<<<(NN + 3) / 4, 128>>>(rowptr, csr_src, as2, ad2, h2, b2, z2);
    decode<<<(NPAIR / 8 * 32 + TPB - 1) / TPB, TPB>>>(pos, neg, z2, out);

    cudaEventDestroy(evX);
    cudaEventDestroy(evG1);
    cudaStreamDestroy(s2);
}

// round 16
// speedup vs baseline: 1.2228x; 1.2228x over previous
#include <cuda_runtime.h>
#include <cuda_fp16.h>
#include <math.h>
#include <stdint.h>

#define NN   30000
#define EE   480000
#define EP   (EE + NN)      // 510000 (edges + self loops)
#define INC  128
#define H1   5
#define C1   64
#define F1   (H1 * C1)      // 320
#define OUTC 64
#define PEC  100000
#define NPAIR (2 * PEC)
#define NEG_SLOPE 0.2f

// ---------------- scratch ----------------
__device__ __half g_h1[NN * F1];
__device__ __half g_h2[NN * OUTC];
__device__ __half g_z2[NN * OUTC];
__device__ float  g_as1[NN * H1];
__device__ float  g_ad1[NN * H1];
__device__ float  g_as2[NN];
__device__ float  g_ad2[NN];
__device__ int    g_cnt[NN];
__device__ int    g_rowptr[NN + 1];
__device__ int    g_cursor[NN];
__device__ int    g_csr_src[EP];
__device__ __half g_xh[NN * INC];
__device__ __half g_z1h[NN * F1];
__device__ __half g_w1h[F1 * INC];   // W1^T [320,128]
__device__ __half g_w2h[OUTC * F1];  // W2^T [64,320]

// ---------------- mma / async helpers (base PTX, sm_80+) ----------------
__device__ __forceinline__ uint32_t smem_u32(const void* p) {
    uint32_t a;
    asm("{ .reg .u64 t; cvta.to.shared.u64 t, %1; cvt.u32.u64 %0, t; }" : "=r"(a) : "l"(p));
    return a;
}
__device__ __forceinline__ void ldsm_x4(uint32_t& r0, uint32_t& r1, uint32_t& r2,
                                        uint32_t& r3, uint32_t addr) {
    asm volatile("ldmatrix.sync.aligned.m8n8.x4.shared.b16 {%0,%1,%2,%3}, [%4];"
                 : "=r"(r0), "=r"(r1), "=r"(r2), "=r"(r3) : "r"(addr));
}
__device__ __forceinline__ void mma_f16(float* c, const uint32_t* a, const uint32_t* b) {
    asm volatile(
        "mma.sync.aligned.m16n8k16.row.col.f32.f16.f16.f32 "
        "{%0,%1,%2,%3}, {%4,%5,%6,%7}, {%8,%9}, {%0,%1,%2,%3};"
        : "+f"(c[0]), "+f"(c[1]), "+f"(c[2]), "+f"(c[3])
        : "r"(a[0]), "r"(a[1]), "r"(a[2]), "r"(a[3]), "r"(b[0]), "r"(b[1]));
}
__device__ __forceinline__ void cp_async16(uint32_t s, const void* g) {
    asm volatile("cp.async.cg.shared.global [%0], [%1], 16;" :: "r"(s), "l"(g));
}
#define CP_COMMIT()  asm volatile("cp.async.commit_group;")
#define CP_WAIT(n)   asm volatile("cp.async.wait_group %0;" :: "n"(n))

// ---- fused prep: float4 x-convert + transpose W1,W2 + 4-wide edge histogram --
__global__ void prep(const float* __restrict__ x, const float* __restrict__ W1,
                     const float* __restrict__ W2, const int* __restrict__ dst,
                     __half* __restrict__ xh,
                     __half* __restrict__ w1h, __half* __restrict__ w2h,
                     int* __restrict__ cnt) {
    int i = blockIdx.x * blockDim.x + threadIdx.x;
    if (i < NN * INC / 4) {
        float4 v = ((const float4*)x)[i];
        ((__half2*)xh)[i * 2]     = __floats2half2_rn(v.x, v.y);
        ((__half2*)xh)[i * 2 + 1] = __floats2half2_rn(v.z, v.w);
    }
    {
        int e0 = i * 4;
        if (e0 < EP) {
            int d[4];
            #pragma unroll
            for (int q = 0; q < 4; q++) {
                int e = e0 + q;
                d[q] = (e < EP) ? ((e < EE) ? dst[e] : e - EE) : -1;
            }
            #pragma unroll
            for (int q = 0; q < 4; q++)
                if (d[q] >= 0) atomicAdd(&cnt[d[q]], 1);
        }
    }
    if (i < INC * F1) {                       // out[n*INC + k] = W1[k*F1 + n]
        int n = i / INC, k = i % INC;
        w1h[i] = __float2half(W1[(size_t)k * F1 + n]);
    }
    if (i < F1 * OUTC) {                      // out[n*F1 + k] = W2[k*OUTC + n]
        int n = i / F1, k = i % F1;
        w2h[i] = __float2half(W2[(size_t)k * OUTC + n]);
    }
}

// ---------------- CSR build: shuffle-based single-block scan (2 barriers) -----
__global__ void scan_all(const int* __restrict__ cnt, int* __restrict__ rowptr,
                         int* __restrict__ cursor) {
    __shared__ int wsum[32];
    const int t = threadIdx.x;
    const int wid = t >> 5, lane = t & 31;
    const int PER = (NN + 1023) / 1024;   // 30
    int local[PER];
    int base = t * PER;
    int sum = 0;
    #pragma unroll
    for (int i = 0; i < PER; i++) {
        int idx = base + i;
        int v = (idx < NN) ? cnt[idx] : 0;
        local[i] = sum;          // exclusive within thread
        sum += v;
    }
    // warp inclusive scan of sums
    int incl = sum;
    #pragma unroll
    for (int o = 1; o < 32; o <<= 1) {
        int u = __shfl_up_sync(0xFFFFFFFFu, incl, o);
        if (lane >= o) incl += u;
    }
    if (lane == 31) wsum[wid] = incl;
    __syncthreads();
    if (wid == 0) {
        int w = (lane < 32) ? wsum[lane] : 0;
        #pragma unroll
        for (int o = 1; o < 32; o <<= 1) {
            int u = __shfl_up_sync(0xFFFFFFFFu, w, o);
            if (lane >= o) w += u;
        }
        wsum[lane] = w - ((lane < 32) ? 0 : 0);   // inclusive warp totals
        // convert to exclusive: store inclusive; consumers subtract
    }
    __syncthreads();
    int warp_excl = (wid > 0) ? wsum[wid - 1] : 0;
    int thread_excl = warp_excl + (incl - sum);
    #pragma unroll
    for (int i = 0; i < PER; i++) {
        int idx = base + i;
        if (idx < NN) {
            int v = thread_excl + local[i];
            rowptr[idx] = v;
            cursor[idx] = v;
        }
    }
    if (t == 0) rowptr[NN] = EP;
}

__global__ void fill_csr(const int* __restrict__ src, const int* __restrict__ dst,
                         int* __restrict__ cursor, int* __restrict__ csr_src) {
    int i = blockIdx.x * blockDim.x + threadIdx.x;
    int e0 = i * 4;
    if (e0 >= EP) return;
    int s[4], d[4];
    #pragma unroll
    for (int q = 0; q < 4; q++) {
        int e = e0 + q;
        if (e < EP) {
            s[q] = (e < EE) ? src[e] : e - EE;
            d[q] = (e < EE) ? dst[e] : e - EE;
        } else d[q] = -1;
    }
    #pragma unroll
    for (int q = 0; q < 4; q++) {
        if (d[q] >= 0) {
            int pos = atomicAdd(&cursor[d[q]], 1);
            csr_src[pos] = s[q];
        }
    }
}

// ======== gemm1: M-tile 64, A-resident, double-buffered B via cp.async ========
#define STRA 136
#define SMA_A  0
#define SMA_B0 (64 * STRA)
#define SMA_B1 (128 * STRA)
#define SMA_RED (192 * STRA)
#define SMA_ELEMS (192 * STRA + 1024)

__global__ void __launch_bounds__(256, 4) gemm1_fused(
    const __half* __restrict__ A, const __half* __restrict__ B,
    __half* __restrict__ Ch,
    float* __restrict__ as_, float* __restrict__ ad_,
    const float* __restrict__ att_s, const float* __restrict__ att_d, int M)
{
    extern __shared__ __align__(16) __half smem[];
    const int tid = threadIdx.x;
    const int wid = tid >> 5, lane = tid & 31;
    const int wm = wid >> 1;
    const int wn = wid & 1;
    const int row0 = blockIdx.x * 64;
    const uint32_t sb = smem_u32(smem);

    #pragma unroll
    for (int i = 0; i < 4; i++) {
        int u = tid + i * 256;
        int r = u >> 4, c8 = (u & 15) * 8;
        int gr = row0 + r;
        uint4 v = (gr < M) ? *(const uint4*)(A + (size_t)gr * INC + c8)
                           : make_uint4(0u, 0u, 0u, 0u);
        *(uint4*)(smem + SMA_A + r * STRA + c8) = v;
    }
    #pragma unroll
    for (int i = 0; i < 4; i++) {
        int u = tid + i * 256;
        int r = u >> 4, c8 = (u & 15) * 8;
        cp_async16(sb + (uint32_t)(SMA_B0 + r * STRA + c8) * 2,
                   B + (size_t)r * INC + c8);
    }
    CP_COMMIT();

    const int a_row = lane & 15;
    const int a_koff = (lane >> 4) * 8;
    const int b_row = (lane & 7) + ((lane >> 4) << 3);
    const int b_koff = ((lane >> 3) & 1) * 8;
    const int erow = lane >> 2;
    const int ecol = (lane & 3) * 2;
    float* red = (float*)(smem + SMA_RED);

    for (int nt = 0; nt < H1; nt++) {
        if (nt + 1 < H1) {
            int bofs_n = ((nt + 1) & 1) ? SMA_B1 : SMA_B0;
            #pragma unroll
            for (int i = 0; i < 4; i++) {
                int u = tid + i * 256;
                int r = u >> 4, c8 = (u & 15) * 8;
                cp_async16(sb + (uint32_t)(bofs_n + r * STRA + c8) * 2,
                           B + (size_t)((nt + 1) * 64 + r) * INC + c8);
            }
            CP_COMMIT();
            CP_WAIT(1);
        } else {
            CP_WAIT(0);
        }
        __syncthreads();

        const int bofs = (nt & 1) ? SMA_B1 : SMA_B0;

        float acc[4][4];
        #pragma unroll
        for (int j = 0; j < 4; j++)
            #pragma unroll
            for (int q = 0; q < 4; q++) acc[j][q] = 0.f;

        #pragma unroll
        for (int ks = 0; ks < 8; ks++) {
            uint32_t ar[4], br[4][2];
            {
                int off = (wm * 16 + a_row) * STRA + ks * 16 + a_koff;
                ldsm_x4(ar[0], ar[1], ar[2], ar[3], sb + (uint32_t)(SMA_A + off) * 2);
            }
            #pragma unroll
            for (int np = 0; np < 2; np++) {
                int off = (wn * 32 + np * 16 + b_row) * STRA + ks * 16 + b_koff;
                ldsm_x4(br[np * 2][0], br[np * 2][1], br[np * 2 + 1][0], br[np * 2 + 1][1],
                        sb + (uint32_t)(bofs + off) * 2);
            }
            #pragma unroll
            for (int ni = 0; ni < 4; ni++)
                mma_f16(acc[ni], ar, br[ni]);
        }

        const int col0 = nt * 64;
        {
            int r0 = row0 + wm * 16 + erow;
            #pragma unroll
            for (int ni = 0; ni < 4; ni++) {
                int cc = col0 + wn * 32 + ni * 8 + ecol;
                if (r0 < M)
                    *(__half2*)&Ch[(size_t)r0 * F1 + cc] =
                        __floats2half2_rn(acc[ni][0], acc[ni][1]);
                if (r0 + 8 < M)
                    *(__half2*)&Ch[(size_t)(r0 + 8) * F1 + cc] =
                        __floats2half2_rn(acc[ni][2], acc[ni][3]);
            }
        }

        const float* att_sg = att_s + nt * 64;
        const float* att_dg = att_d + nt * 64;
        float asp[2] = {}, adp[2] = {};
        #pragma unroll
        for (int ni = 0; ni < 4; ni++) {
            int cb = wn * 32 + ni * 8 + ecol;
            float s0 = att_sg[cb], s1 = att_sg[cb + 1];
            float d0 = att_dg[cb], d1 = att_dg[cb + 1];
            asp[0] += acc[ni][0] * s0 + acc[ni][1] * s1;
            asp[1] += acc[ni][2] * s0 + acc[ni][3] * s1;
            adp[0] += acc[ni][0] * d0 + acc[ni][1] * d1;
            adp[1] += acc[ni][2] * d0 + acc[ni][3] * d1;
        }
        #pragma unroll
        for (int o = 1; o < 4; o <<= 1) {
            #pragma unroll
            for (int mr = 0; mr < 2; mr++) {
                asp[mr] += __shfl_xor_sync(0xFFFFFFFFu, asp[mr], o);
                adp[mr] += __shfl_xor_sync(0xFFFFFFFFu, adp[mr], o);
            }
        }
        if ((lane & 3) == 0) {
            #pragma unroll
            for (int mr = 0; mr < 2; mr++) {
                int rl = wm * 16 + erow + mr * 8;
                red[rl * 4 + wn]     = asp[mr];
                red[rl * 4 + 2 + wn] = adp[mr];
            }
        }
        __syncthreads();
        if (tid < 64) {
            int r = row0 + tid;
            if (r < M) {
                as_[(size_t)r * H1 + nt] = red[tid * 4 + 0] + red[tid * 4 + 1];
                ad_[(size_t)r * H1 + nt] = red[tid * 4 + 2] + red[tid * 4 + 3];
            }
        }
    }
}

// ======== gemm2: chunked-K fp16 HMMA (K=320), N tile 64, logits fused ========
#define STR 72
#define SM_A 0
#define SM_B (128 * STR)
#define SM_ELEMS (128 * STR + 64 * STR)

__global__ void __launch_bounds__(256, 4) mma_gemm(
    const __half* __restrict__ A, const __half* __restrict__ B,
    __half* __restrict__ Ch,
    float* __restrict__ as_, float* __restrict__ ad_,
    const float* __restrict__ att_s, const float* __restrict__ att_d,
    int M, int Ncol, int K, int H)
{
    extern __shared__ __align__(16) __half smem[];
    const int tid = threadIdx.x;
    const int wid = tid >> 5, lane = tid & 31;
    const int wm = wid >> 1;
    const int wn = wid & 1;
    const int row0 = blockIdx.y * 128;
    const int col0 = blockIdx.x * 64;
    const int hx = blockIdx.x;
    const uint32_t sb = smem_u32(smem);

    float acc[2][4][4];
    #pragma unroll
    for (int i = 0; i < 2; i++)
        #pragma unroll
        for (int j = 0; j < 4; j++)
            #pragma unroll
            for (int q = 0; q < 4; q++) acc[i][j][q] = 0.f;

    const int a_row = lane & 15;
    const int a_koff = (lane >> 4) * 8;
    const int b_row = (lane & 7) + ((lane >> 4) << 3);
    const int b_koff = ((lane >> 3) & 1) * 8;

    for (int K0 = 0; K0 < K; K0 += 64) {
        #pragma unroll
        for (int i = 0; i < 4; i++) {
            int u = tid + i * 256;
            int r = u >> 3, c8 = (u & 7) * 8;
            int dstoff = r * STR + c8;
            int gr = row0 + r;
            uint4 v = (gr < M) ? *(const uint4*)(A + (size_t)gr * K + K0 + c8)
                               : make_uint4(0u, 0u, 0u, 0u);
            *(uint4*)(smem + SM_A + dstoff) = v;
        }
        #pragma unroll
        for (int i = 0; i < 2; i++) {
            int u = tid + i * 256;
            int r = u >> 3, c8 = (u & 7) * 8;
            int dstoff = r * STR + c8;
            *(uint4*)(smem + SM_B + dstoff) = *(const uint4*)(B + (size_t)(col0 + r) * K + K0 + c8);
        }
        __syncthreads();

        #pragma unroll
        for (int ks = 0; ks < 4; ks++) {
            uint32_t ar[2][4], br[4][2];
            #pragma unroll
            for (int mi = 0; mi < 2; mi++) {
                int off = (wm * 32 + mi * 16 + a_row) * STR + ks * 16 + a_koff;
                ldsm_x4(ar[mi][0], ar[mi][1], ar[mi][2], ar[mi][3],
                        sb + (uint32_t)(SM_A + off) * 2);
            }
            #pragma unroll
            for (int np = 0; np < 2; np++) {
                int off = (wn * 32 + np * 16 + b_row) * STR + ks * 16 + b_koff;
                ldsm_x4(br[np * 2][0], br[np * 2][1], br[np * 2 + 1][0], br[np * 2 + 1][1],
                        sb + (uint32_t)(SM_B + off) * 2);
            }
            #pragma unroll
            for (int mi = 0; mi < 2; mi++)
                #pragma unroll
                for (int ni = 0; ni < 4; ni++)
                    mma_f16(acc[mi][ni], ar[mi], br[ni]);
        }
        __syncthreads();
    }

    const int erow = lane >> 2;
    const int ecol = (lane & 3) * 2;

    #pragma unroll
    for (int mi = 0; mi < 2; mi++) {
        int r0 = row0 + wm * 32 + mi * 16 + erow;
        #pragma unroll
        for (int ni = 0; ni < 4; ni++) {
            int cc = col0 + wn * 32 + ni * 8 + ecol;
            if (r0 < M)
                *(__half2*)&Ch[(size_t)r0 * Ncol + cc] =
                    __floats2half2_rn(acc[mi][ni][0], acc[mi][ni][1]);
            if (r0 + 8 < M)
                *(__half2*)&Ch[(size_t)(r0 + 8) * Ncol + cc] =
                    __floats2half2_rn(acc[mi][ni][2], acc[mi][ni][3]);
        }
    }

    const float* att_sg = att_s + hx * 64;
    const float* att_dg = att_d + hx * 64;
    float asp[2][2] = {}, adp[2][2] = {};
    #pragma unroll
    for (int mi = 0; mi < 2; mi++)
        #pragma unroll
        for (int ni = 0; ni < 4; ni++) {
            int cb = wn * 32 + ni * 8 + ecol;
            float s0 = att_sg[cb], s1 = att_sg[cb + 1];
            float d0 = att_dg[cb], d1 = att_dg[cb + 1];
            asp[mi][0] += acc[mi][ni][0] * s0 + acc[mi][ni][1] * s1;
            asp[mi][1] += acc[mi][ni][2] * s0 + acc[mi][ni][3] * s1;
            adp[mi][0] += acc[mi][ni][0] * d0 + acc[mi][ni][1] * d1;
            adp[mi][1] += acc[mi][ni][2] * d0 + acc[mi][ni][3] * d1;
        }
    #pragma unroll
    for (int o = 1; o < 4; o <<= 1) {
        #pragma unroll
        for (int mi = 0; mi < 2; mi++)
            #pragma unroll
            for (int mr = 0; mr < 2; mr++) {
                asp[mi][mr] += __shfl_xor_sync(0xFFFFFFFFu, asp[mi][mr], o);
                adp[mi][mr] += __shfl_xor_sync(0xFFFFFFFFu, adp[mi][mr], o);
            }
    }
    float* red = (float*)smem;
    if ((lane & 3) == 0) {
        #pragma unroll
        for (int mi = 0; mi < 2; mi++)
            #pragma unroll
            for (int mr = 0; mr < 2; mr++) {
                int rl = wm * 32 + mi * 16 + erow + mr * 8;
                red[rl * 4 + wn]     = asp[mi][mr];
                red[rl * 4 + 2 + wn] = adp[mi][mr];
            }
    }
    __syncthreads();
    if (tid < 128) {
        int r = row0 + tid;
        if (r < M) {
            as_[(size_t)r * H + hx] = red[tid * 4 + 0] + red[tid * 4 + 1];
            ad_[(size_t)r * H + hx] = red[tid * 4 + 2] + red[tid * 4 + 3];
        }
    }
}

// ---------------- fused softmax + aggregate + relu, layer 1 ----------------
__global__ void agg1(const int* __restrict__ rowptr, const int* __restrict__ csr_src,
                     const float* __restrict__ as_, const float* __restrict__ ad_,
                     const __half* __restrict__ h, const float* __restrict__ bias,
                     __half* __restrict__ zh) {
    __shared__ int   sh_src[32];
    __shared__ float sh_ex[160];
    const int d = blockIdx.x;
    const int c = threadIdx.x;
    const int hh = c >> 5;
    const int start = rowptr[d], end = rowptr[d + 1];
    const __half2* hp = (const __half2*)h;

    float ax = 0.f, ay = 0.f, sumex = 0.f;
    for (int j0 = start; j0 < end; j0 += 32) {
        int m = min(32, end - j0);
        {
            int j = c & 31, hq = c >> 5;
            if (j < m) {
                int s = csr_src[j0 + j];
                if (hq == 0) sh_src[j] = s;
                float e = as_[s * H1 + hq] + ad_[d * H1 + hq];
                e = (e > 0.f) ? e : NEG_SLOPE * e;
                sh_ex[hq * 32 + j] = __expf(e);
            }
        }
        __syncthreads();
        #pragma unroll 4
        for (int j = 0; j < m; j++) {
            float ex = sh_ex[hh * 32 + j];
            sumex += ex;
            float2 f = __half22float2(hp[(size_t)sh_src[j] * (F1 / 2) + c]);
            ax += ex * f.x;
            ay += ex * f.y;
        }
        __syncthreads();
    }
    float inv = 1.f / (sumex + 1e-16f);
    float v0 = ax * inv + bias[2 * c];
    float v1 = ay * inv + bias[2 * c + 1];
    v0 = (v0 > 0.f) ? v0 : 0.f;
    v1 = (v1 > 0.f) ? v1 : 0.f;
    ((__half2*)zh)[(size_t)d * (F1 / 2) + c] = __floats2half2_rn(v0, v1);
}

// ------- fused softmax + aggregate, layer 2: 4 nodes per 128-thr block -------
__global__ void agg2(const int* __restrict__ rowptr, const int* __restrict__ csr_src,
                     const float* __restrict__ as_, const float* __restrict__ ad_,
                     const __half* __restrict__ h, const float* __restrict__ bias,
                     __half* __restrict__ z) {
    const int d = blockIdx.x * 4 + (threadIdx.x >> 5);
    const int c = threadIdx.x & 31;
    if (d >= NN) return;
    const int start = rowptr[d], end = rowptr[d + 1];
    const __half2* hp = (const __half2*)h;

    float ax = 0.f, ay = 0.f, sumex = 0.f;
    for (int j0 = start; j0 < end; j0 += 32) {
        int m = min(32, end - j0);
        int s_c = 0; float ex_c = 0.f;
        if (c < m) {
            s_c = csr_src[j0 + c];
            float e = as_[s_c] + ad_[d];
            e = (e > 0.f) ? e : NEG_SLOPE * e;
            ex_c = __expf(e);
        }
        #pragma unroll 4
        for (int j = 0; j < m; j++) {
            float ex = __shfl_sync(0xFFFFFFFFu, ex_c, j);
            int   s  = __shfl_sync(0xFFFFFFFFu, s_c, j);
            sumex += ex;
            float2 f = __half22float2(hp[(size_t)s * (OUTC / 2) + c]);
            ax += ex * f.x;
            ay += ex * f.y;
        }
    }
    float inv = 1.f / (sumex + 1e-16f);
    ((__half2*)z)[(size_t)d * (OUTC / 2) + c] =
        __floats2half2_rn(ax * inv + bias[2 * c], ay * inv + bias[2 * c + 1]);
}

// ---- decode: 8 pairs per warp (2 per 8-lane subgroup), uint4 loads, MLP=4 ----
__global__ void decode(const int* __restrict__ pos, const int* __restrict__ neg,
                       const __half* __restrict__ z, float* __restrict__ out) {
    int g = blockIdx.x * blockDim.x + threadIdx.x;
    int w = g >> 5, lane = g & 31;
    int sub = lane >> 3;
    int l = lane & 7;
    int p0 = w * 8 + sub * 2;
    if (p0 >= NPAIR) return;
    float v[2] = {0.f, 0.f};
    #pragma unroll
    for (int t = 0; t < 2; t++) {
        int p = p0 + t;
        if (p >= NPAIR) break;
        int i, j;
        if (p < PEC) { i = pos[p];       j = pos[PEC + p]; }
        else         { i = neg[p - PEC]; j = neg[PEC + p - PEC]; }
        uint4 a = ((const uint4*)(z + (size_t)i * OUTC))[l];
        uint4 b = ((const uint4*)(z + (size_t)j * OUTC))[l];
        const __half2* ah = (const __half2*)&a;
        const __half2* bh = (const __half2*)&b;
        #pragma unroll
        for (int q = 0; q < 4; q++) {
            float2 fa = __half22float2(ah[q]);
            float2 fb = __half22float2(bh[q]);
            v[t] += fa.x * fb.x + fa.y * fb.y;
        }
    }
    #pragma unroll
    for (int o = 4; o > 0; o >>= 1) {
        v[0] += __shfl_down_sync(0xFFFFFFFFu, v[0], o, 8);
        v[1] += __shfl_down_sync(0xFFFFFFFFu, v[1], o, 8);
    }
    if (l == 0) {
        out[p0] = v[0];
        if (p0 + 1 < NPAIR) out[p0 + 1] = v[1];
    }
}

// ---------------- launch ----------------
extern "C" void kernel_launch(void* const* d_in, const int* in_sizes, int n_in,
                              void* d_out, int out_size) {
    const float* x      = (const float*)d_in[0];
    const int*   ei     = (const int*)  d_in[1];
    const int*   pos    = (const int*)  d_in[2];
    const int*   neg    = (const int*)  d_in[3];
    const float* W1     = (const float*)d_in[4];
    const float* att_s1 = (const float*)d_in[5];
    const float* att_d1 = (const float*)d_in[6];
    const float* b1     = (const float*)d_in[7];
    const float* W2     = (const float*)d_in[8];
    const float* att_s2 = (const float*)d_in[9];
    const float* att_d2 = (const float*)d_in[10];
    const float* b2     = (const float*)d_in[11];
    float* out = (float*)d_out;

    const int* src = ei;
    const int* dst = ei + EE;

    __half *h1, *h2, *z2, *xh, *z1h, *w1h, *w2h;
    float *as1, *ad1, *as2, *ad2;
    int *cnt, *rowptr, *cursor, *csr_src;
    cudaGetSymbolAddress((void**)&h1, g_h1);
    cudaGetSymbolAddress((void**)&h2, g_h2);
    cudaGetSymbolAddress((void**)&z2, g_z2);
    cudaGetSymbolAddress((void**)&as1, g_as1);
    cudaGetSymbolAddress((void**)&ad1, g_ad1);
    cudaGetSymbolAddress((void**)&as2, g_as2);
    cudaGetSymbolAddress((void**)&ad2, g_ad2);
    cudaGetSymbolAddress((void**)&cnt, g_cnt);
    cudaGetSymbolAddress((void**)&rowptr, g_rowptr);
    cudaGetSymbolAddress((void**)&cursor, g_cursor);
    cudaGetSymbolAddress((void**)&csr_src, g_csr_src);
    cudaGetSymbolAddress((void**)&xh, g_xh);
    cudaGetSymbolAddress((void**)&z1h, g_z1h);
    cudaGetSymbolAddress((void**)&w1h, g_w1h);
    cudaGetSymbolAddress((void**)&w2h, g_w2h);

    const int TPB = 256;
    constexpr int SMEM_G1 = SMA_ELEMS * 2;
    constexpr int SMEM_G2 = SM_ELEMS * 2;
    cudaFuncSetAttribute(gemm1_fused, cudaFuncAttributeMaxDynamicSharedMemorySize, SMEM_G1);
    cudaFuncSetAttribute(mma_gemm, cudaFuncAttributeMaxDynamicSharedMemorySize, SMEM_G2);

    cudaStream_t s2;
    cudaStreamCreate(&s2);
    cudaEvent_t evPrep, evG1;
    cudaEventCreateWithFlags(&evPrep, cudaEventDisableTiming);
    cudaEventCreateWithFlags(&evG1, cudaEventDisableTiming);

    // ---- prep (+hist) ----
    cudaMemsetAsync(cnt, 0, NN * sizeof(int));
    prep<<<(NN * INC / 4 + TPB - 1) / TPB, TPB>>>(x, W1, W2, dst, xh, w1h, w2h, cnt);
    cudaEventRecord(evPrep, 0);

    // ---- CSR build (stream 0) || gemm1 (stream s2) ----
    scan_all<<<1, 1024>>>(cnt, rowptr, cursor);
    fill_csr<<<(EP / 4 + TPB) / TPB, TPB>>>(src, dst, cursor, csr_src);

    cudaStreamWaitEvent(s2, evPrep, 0);
    gemm1_fused<<<(NN + 63) / 64, 256, SMEM_G1, s2>>>(
        xh, w1h, h1, as1, ad1, att_s1, att_d1, NN);
    cudaEventRecord(evG1, s2);
    cudaStreamWaitEvent(0, evG1, 0);

    // ---- layer 1 aggregate -> layer 2 GEMM -> aggregate -> decode ----
    agg1<<<NN, 160>>>(rowptr, csr_src, as1, ad1, h1, b1, z1h);
    {
        dim3 grid(1, (NN + 127) / 128);
        mma_gemm<<<grid, 256, SMEM_G2>>>(z1h, w2h, h2,
                                         as2, ad2, att_s2, att_d2, NN, OUTC, F1, 1);
    }
    agg2<<<(NN + 3) / 4, 128>>>(rowptr, csr_src, as2, ad2, h2, b2, z2);
    decode<<<(NPAIR / 8 * 32 + TPB - 1) / TPB, TPB>>>(pos, neg, z2, out);

    cudaEventDestroy(evPrep);
    cudaEventDestroy(evG1);
    cudaStreamDestroy(s2);
}